// round 8
// baseline (speedup 1.0000x reference)
#include <cuda_runtime.h>
#include <cuda_bf16.h>

// VQ codebook quantization — FFMA2, X8×Y4 lane map, min-wavefront layouts.
//   s[n,k] = z[n]·e[k] - 0.5*||e[k]||^2 ; idx[n] = argmax_k s ; out = e[idx]
// N=65536, D=64, K=1024. Output: [N*D quantized][N indices-as-float].
//
// Block 256, TM=128, TKC=32. tx=tid&7 (codes tx+8j), ty=tid>>3 (rows ty+32i).
// Per-thread 4 rows x 4 codes. Per warp-kk2: 4 z LDS.128 (4 consecutive rows
// @ pitch-17-float4 -> 1 wavefront) + 4 e LDS.128 (8 distinct codes @
// pitch-33-float4 -> 1 wavefront) + 32 FFMA2 -> wf:fma = 8:16 SM-cycles.
// ~95 regs leaves ptxas headroom to pipeline loads (R6's missing piece).

#define DDIM 64
#define TM 128
#define TKC 32
#define ZPITCH4 17    // float4 per padded z row
#define EPITCH4 33    // float4 per padded e row
#define KMAX 4096

__device__ float g_cnorm[KMAX];

__global__ void cnorm_kernel(const float* __restrict__ emb, int K) {
    int k = blockIdx.x * blockDim.x + threadIdx.x;
    if (k < K) {
        const float4* e4 = reinterpret_cast<const float4*>(emb + (size_t)k * DDIM);
        float s = 0.f;
#pragma unroll
        for (int i = 0; i < DDIM / 4; i++) {
            float4 v = e4[i];
            s += v.x * v.x + v.y * v.y + v.z * v.z + v.w * v.w;
        }
        g_cnorm[k] = 0.5f * s;
    }
}

#define FMA2(acc, a, b) \
    asm("fma.rn.f32x2 %0, %1, %2, %0;" : "+l"(acc) : "l"(a), "l"(b))

__global__ __launch_bounds__(256, 2)
void vq_kernel(const float* __restrict__ z, const float* __restrict__ emb,
               float* __restrict__ out, int N, int K, int write_idx) {
    extern __shared__ float smem[];
    float* zs = smem;                                // TM*ZPITCH4*4 floats (34 KB)
    float* es = smem + TM * ZPITCH4 * 4;             // TKC*EPITCH4*4 floats (16.5 KB)
    float* cns = es + TKC * EPITCH4 * 4;             // TKC
    int* finalIdx = (int*)(cns + TKC);               // TM

    const int tid = threadIdx.x;
    const int tx = tid & 7;        // codes tx + 8*j, j=0..3
    const int ty = tid >> 3;       // rows ty + 32*i, i=0..3
    const int rowBase = blockIdx.x * TM;

    // stage z tile at pitch 17 float4 (aligned float4 stores)
#pragma unroll
    for (int t = 0; t < (TM * DDIM / 4) / 256; t++) {   // 8 iters
        int idx = tid + t * 256;
        int row = idx >> 4;
        int c4 = idx & 15;
        reinterpret_cast<float4*>(zs)[row * ZPITCH4 + c4] =
            reinterpret_cast<const float4*>(z + (size_t)(rowBase + row) * DDIM)[c4];
    }

    float best[4];
    int bidx[4];
#pragma unroll
    for (int i = 0; i < 4; i++) { best[i] = -3.402823466e38f; bidx[i] = 0; }

    const ulonglong2* zs4 = reinterpret_cast<const ulonglong2*>(zs);
    const ulonglong2* es4 = reinterpret_cast<const ulonglong2*>(es);

    for (int kc = 0; kc < K; kc += TKC) {
        __syncthreads();
        // stage e chunk: 32 codes x 16 float4, pitch 33 (aligned); 2/thread
        {
            const float4* src = reinterpret_cast<const float4*>(
                emb + (size_t)kc * DDIM);
            float4* dst = reinterpret_cast<float4*>(es);
#pragma unroll
            for (int t = 0; t < (TKC * DDIM / 4) / 256; t++) {  // 2 iters
                int idx = tid + t * 256;
                int code = idx >> 4;
                int c4 = idx & 15;
                dst[code * EPITCH4 + c4] = src[code * 16 + c4];
            }
        }
        if (tid < TKC) cns[tid] = g_cnorm[kc + tid];
        __syncthreads();

        unsigned long long acc[4][4];
#pragma unroll
        for (int i = 0; i < 4; i++)
#pragma unroll
            for (int j = 0; j < 4; j++) acc[i][j] = 0ull;

#pragma unroll
        for (int kk2 = 0; kk2 < DDIM / 4; kk2++) {   // 16 steps, 4 dims each
            ulonglong2 zz[4];
#pragma unroll
            for (int i = 0; i < 4; i++)
                zz[i] = zs4[(ty + 32 * i) * ZPITCH4 + kk2];   // 1 wavefront
            ulonglong2 ee[4];
#pragma unroll
            for (int j = 0; j < 4; j++)
                ee[j] = es4[(tx + 8 * j) * EPITCH4 + kk2];    // 1 wavefront
#pragma unroll
            for (int i = 0; i < 4; i++)
#pragma unroll
                for (int j = 0; j < 4; j++) {
                    FMA2(acc[i][j], zz[i].x, ee[j].x);
                    FMA2(acc[i][j], zz[i].y, ee[j].y);
                }
        }

        // fold into running per-row argmax
#pragma unroll
        for (int j = 0; j < 4; j++) {
            int code = kc + tx + 8 * j;
            float cn = cns[tx + 8 * j];
#pragma unroll
            for (int i = 0; i < 4; i++) {
                float lo, hi;
                asm("mov.b64 {%0, %1}, %2;" : "=f"(lo), "=f"(hi) : "l"(acc[i][j]));
                float s = (lo + hi) - cn;
                if (s > best[i]) { best[i] = s; bidx[i] = code; }
            }
        }
    }

    __syncthreads();
    // cross-tx reduction over 8 code-lanes (explicit index tie-break)
    float* rval = es;                       // [TM][8]
    int* ridx = (int*)(es + TM * 8);        // [TM][8]
#pragma unroll
    for (int i = 0; i < 4; i++) {
        rval[(ty + 32 * i) * 8 + tx] = best[i];
        ridx[(ty + 32 * i) * 8 + tx] = bidx[i];
    }
    __syncthreads();
    if (tid < TM) {
        float b = rval[tid * 8 + 0];
        int bi = ridx[tid * 8 + 0];
#pragma unroll
        for (int t = 1; t < 8; t++) {
            float v = rval[tid * 8 + t];
            int vi = ridx[tid * 8 + t];
            if (v > b || (v == b && vi < bi)) { b = v; bi = vi; }
        }
        finalIdx[tid] = bi;
        if (write_idx)
            out[(size_t)N * DDIM + rowBase + tid] = (float)bi;
    }
    __syncthreads();

    // gather quantized rows (emb rows are L2-hot)
#pragma unroll
    for (int t = 0; t < (TM * DDIM / 4) / 256; t++) {
        int idx = tid + t * 256;
        int row = idx >> 4;
        int c4 = idx & 15;
        float4 v = reinterpret_cast<const float4*>(
            emb + (size_t)finalIdx[row] * DDIM)[c4];
        reinterpret_cast<float4*>(out + (size_t)(rowBase + row) * DDIM)[c4] = v;
    }
}

extern "C" void kernel_launch(void* const* d_in, const int* in_sizes, int n_in,
                              void* d_out, int out_size) {
    const float* z = (const float*)d_in[0];
    const float* emb = (const float*)d_in[1];
    if (n_in >= 2 && in_sizes[1] > in_sizes[0]) {
        const float* t = z; z = emb; emb = t;
    }
    int zsize = in_sizes[0], esize = in_sizes[1];
    if (esize > zsize) { int t = zsize; zsize = esize; esize = t; }

    int N = zsize / DDIM;   // 65536
    int K = esize / DDIM;   // 1024
    float* out = (float*)d_out;
    int write_idx = (out_size >= N * DDIM + N) ? 1 : 0;

    cnorm_kernel<<<(K + 255) / 256, 256>>>(emb, K);

    int smem_bytes = (TM * ZPITCH4 * 4 + TKC * EPITCH4 * 4 + TKC)
                         * (int)sizeof(float)
                     + TM * (int)sizeof(int);   // ~51.5 KB
    static int attr_set = 0;
    if (!attr_set) {
        cudaFuncSetAttribute(vq_kernel, cudaFuncAttributeMaxDynamicSharedMemorySize,
                             smem_bytes);
        attr_set = 1;
    }
    vq_kernel<<<N / TM, 256, smem_bytes>>>(z, emb, out, N, K, write_idx);
}

// round 10
// speedup vs baseline: 2.3632x; 2.3632x over previous
#include <cuda_runtime.h>
#include <cuda_bf16.h>
#include <cstdint>

// VQ codebook quantization via mma.sync bf16 (3-term split, fp32-exact).
//   s[n,k] = z[n]·e[k] - 0.5*||e[k]||^2 ; idx[n] = argmax_k s ; out = e[idx]
// N=65536, D=64, K=1024. Output: [N*D quantized][N indices-as-float].
//
// tcgen05 is arch-gated (harness compiles PTX at compute_103 family target),
// so use baseline-PTX tensor cores: mma.sync.m16n8k16.row.col.f32.bf16 +
// ldmatrix. z=zh+zl, e=eh+el (bf16); D = zh·eh + zh·el + zl·eh in f32
// (dropped zl·el ~2^-16 relative -> argmin identical to fp32).
// CTA 256thr/8 warps/128 rows; warp owns 16 rows, A-frags in regs (built once
// from gmem). e chunk (64 codes) staged at pitch-144B -> conflict-free
// ldmatrix.x4. 12 MMA per 8-code tile; per-lane argmax fold; quad-shfl reduce.

#define DDIM 64
#define TKC  64
#define EPB  144          // bytes per e row in smem (conflict-free ldmatrix)
#define KMAX 1024

__device__ float g_cnorm[KMAX];
__device__ __align__(16) __nv_bfloat16 g_eh[KMAX * DDIM];
__device__ __align__(16) __nv_bfloat16 g_el[KMAX * DDIM];

__global__ void prep_kernel(const float* __restrict__ emb, int K) {
    int k = blockIdx.x * blockDim.x + threadIdx.x;
    if (k < K) {
        float s = 0.f;
#pragma unroll
        for (int d = 0; d < DDIM; d++) {
            float v = emb[(size_t)k * DDIM + d];
            s += v * v;
            __nv_bfloat16 h = __float2bfloat16(v);
            g_eh[(size_t)k * DDIM + d] = h;
            g_el[(size_t)k * DDIM + d] =
                __float2bfloat16(v - __bfloat162float(h));
        }
        g_cnorm[k] = 0.5f * s;
    }
}

__device__ __forceinline__ uint32_t smem_u32(const void* p) {
    uint32_t a;
    asm("{ .reg .u64 t; cvta.to.shared.u64 t, %1; cvt.u32.u64 %0, t; }"
        : "=r"(a) : "l"(p));
    return a;
}
__device__ __forceinline__ uint32_t pack_bf16x2(float x, float y) {
    __nv_bfloat162 h;
    h.x = __float2bfloat16(x);
    h.y = __float2bfloat16(y);
    return *reinterpret_cast<uint32_t*>(&h);
}
__device__ __forceinline__ uint32_t pack_res(float x, float y, uint32_t hp) {
    __nv_bfloat162 h = *reinterpret_cast<__nv_bfloat162*>(&hp);
    __nv_bfloat162 l;
    l.x = __float2bfloat16(x - __bfloat162float(h.x));
    l.y = __float2bfloat16(y - __bfloat162float(h.y));
    return *reinterpret_cast<uint32_t*>(&l);
}
#define MMA16816(d0, d1, d2, d3, a0, a1, a2, a3, b0, b1) \
    asm volatile( \
        "mma.sync.aligned.m16n8k16.row.col.f32.bf16.bf16.f32 " \
        "{%0,%1,%2,%3},{%4,%5,%6,%7},{%8,%9},{%0,%1,%2,%3};" \
        : "+f"(d0), "+f"(d1), "+f"(d2), "+f"(d3) \
        : "r"(a0), "r"(a1), "r"(a2), "r"(a3), "r"(b0), "r"(b1))
#define LDMX4(r0, r1, r2, r3, a) \
    asm volatile("ldmatrix.sync.aligned.m8n8.x4.shared.b16 {%0,%1,%2,%3}, [%4];" \
                 : "=r"(r0), "=r"(r1), "=r"(r2), "=r"(r3) : "r"(a))

__global__ __launch_bounds__(256, 2)
void vq_kernel(const float* __restrict__ z, const float* __restrict__ emb,
               float* __restrict__ out, int N, int K, int write_idx) {
    __shared__ float cns[KMAX];                       // 4 KB
    __shared__ __align__(16) char eh_sm[TKC * EPB];   // 9 KB
    __shared__ __align__(16) char el_sm[TKC * EPB];   // 9 KB
    __shared__ int finalIdx[128];

    const int tid = threadIdx.x;
    const int wid = tid >> 5;
    const int lane = tid & 31;
    const int qid = lane >> 2;       // 0..7
    const int qsub = lane & 3;       // 0..3
    const int rowBase = blockIdx.x * 128;

    // ---- build A fragments (zh/zl) for 4 k-steps, once, from gmem ----
    // a0:(m,klo) a1:(m+8,klo) a2:(m,khi) a3:(m+8,khi); m = qid, k pairs by qsub
    uint32_t ah[4][4], al[4][4];
    {
        const int r0 = rowBase + wid * 16 + qid;
        const int r1 = r0 + 8;
#pragma unroll
        for (int ks = 0; ks < 4; ks++) {
            int k0 = ks * 16 + qsub * 2;
            float2 v00 = *reinterpret_cast<const float2*>(z + (size_t)r0 * DDIM + k0);
            float2 v01 = *reinterpret_cast<const float2*>(z + (size_t)r0 * DDIM + k0 + 8);
            float2 v10 = *reinterpret_cast<const float2*>(z + (size_t)r1 * DDIM + k0);
            float2 v11 = *reinterpret_cast<const float2*>(z + (size_t)r1 * DDIM + k0 + 8);
            ah[ks][0] = pack_bf16x2(v00.x, v00.y);
            ah[ks][1] = pack_bf16x2(v10.x, v10.y);
            ah[ks][2] = pack_bf16x2(v01.x, v01.y);
            ah[ks][3] = pack_bf16x2(v11.x, v11.y);
            al[ks][0] = pack_res(v00.x, v00.y, ah[ks][0]);
            al[ks][1] = pack_res(v10.x, v10.y, ah[ks][1]);
            al[ks][2] = pack_res(v01.x, v01.y, ah[ks][2]);
            al[ks][3] = pack_res(v11.x, v11.y, ah[ks][3]);
        }
    }
    // ---- stage all cnorms ----
    for (int i = tid; i < K; i += 256) cns[i] = g_cnorm[i];

    const uint32_t eh_b = smem_u32(eh_sm);
    const uint32_t el_b = smem_u32(el_sm);

    float bestA = -3.402823466e38f, bestB = -3.402823466e38f;
    int bidxA = 0, bidxB = 0;

    const int nchunks = K / TKC;
    for (int c = 0; c < nchunks; c++) {
        __syncthreads();
        // stage e chunk: 64 codes x 8 uint4 per term (pitch 144 B)
        {
            const uint4* sh = reinterpret_cast<const uint4*>(
                g_eh + (size_t)c * TKC * DDIM);
            const uint4* sl = reinterpret_cast<const uint4*>(
                g_el + (size_t)c * TKC * DDIM);
#pragma unroll
            for (int t = 0; t < 2; t++) {
                int u = tid + t * 256;
                int code = u >> 3, q = u & 7;
                *reinterpret_cast<uint4*>(eh_sm + code * EPB + q * 16) =
                    sh[code * 8 + q];
                *reinterpret_cast<uint4*>(el_sm + code * EPB + q * 16) =
                    sl[code * 8 + q];
            }
        }
        __syncthreads();

#pragma unroll
        for (int nt = 0; nt < 8; nt++) {
            // ldmatrix addresses: matrix = lane/8 (k-block), row-in = lane%8 (code)
            uint32_t lm_off = (nt * 8 + (lane & 7)) * EPB + (lane >> 3) * 16;
            uint32_t bh[8], bl[8];
            LDMX4(bh[0], bh[1], bh[2], bh[3], eh_b + lm_off);        // k 0..31
            LDMX4(bh[4], bh[5], bh[6], bh[7], eh_b + lm_off + 64);   // k 32..63
            LDMX4(bl[0], bl[1], bl[2], bl[3], el_b + lm_off);
            LDMX4(bl[4], bl[5], bl[6], bl[7], el_b + lm_off + 64);

            float d0 = 0.f, d1 = 0.f, d2 = 0.f, d3 = 0.f;
#pragma unroll
            for (int ks = 0; ks < 4; ks++) {
                MMA16816(d0, d1, d2, d3, ah[ks][0], ah[ks][1], ah[ks][2], ah[ks][3],
                         bh[2 * ks], bh[2 * ks + 1]);
                MMA16816(d0, d1, d2, d3, ah[ks][0], ah[ks][1], ah[ks][2], ah[ks][3],
                         bl[2 * ks], bl[2 * ks + 1]);
                MMA16816(d0, d1, d2, d3, al[ks][0], al[ks][1], al[ks][2], al[ks][3],
                         bh[2 * ks], bh[2 * ks + 1]);
            }

            // fold: rows (qid, qid+8), cols (code0, code0+1); codes ascend
            int code0 = c * TKC + nt * 8 + qsub * 2;
            float2 cn = *reinterpret_cast<const float2*>(&cns[code0]);
            float s0 = d0 - cn.x, s1 = d1 - cn.y;
            float s2 = d2 - cn.x, s3 = d3 - cn.y;
            if (s0 > bestA) { bestA = s0; bidxA = code0; }
            if (s1 > bestA) { bestA = s1; bidxA = code0 + 1; }
            if (s2 > bestB) { bestB = s2; bidxB = code0; }
            if (s3 > bestB) { bestB = s3; bidxB = code0 + 1; }
        }
    }

    // ---- quad-lane reduce (same row in lanes 4q..4q+3), index tie-break ----
#pragma unroll
    for (int off = 1; off < 4; off <<= 1) {
        float vA = __shfl_xor_sync(0xFFFFFFFFu, bestA, off);
        int iA = __shfl_xor_sync(0xFFFFFFFFu, bidxA, off);
        if (vA > bestA || (vA == bestA && iA < bidxA)) { bestA = vA; bidxA = iA; }
        float vB = __shfl_xor_sync(0xFFFFFFFFu, bestB, off);
        int iB = __shfl_xor_sync(0xFFFFFFFFu, bidxB, off);
        if (vB > bestB || (vB == bestB && iB < bidxB)) { bestB = vB; bidxB = iB; }
    }
    if (qsub == 0) {
        finalIdx[wid * 16 + qid] = bidxA;
        finalIdx[wid * 16 + qid + 8] = bidxB;
    }
    __syncthreads();

    if (write_idx && tid < 128)
        out[(size_t)N * DDIM + rowBase + tid] = (float)finalIdx[tid];

    // ---- gather quantized rows (emb rows L2-hot) ----
#pragma unroll
    for (int t = 0; t < 8; t++) {
        int idx = tid + t * 256;
        int row = idx >> 4;
        int c4 = idx & 15;
        float4 v = reinterpret_cast<const float4*>(
            emb + (size_t)finalIdx[row] * DDIM)[c4];
        reinterpret_cast<float4*>(out + (size_t)(rowBase + row) * DDIM)[c4] = v;
    }
}

extern "C" void kernel_launch(void* const* d_in, const int* in_sizes, int n_in,
                              void* d_out, int out_size) {
    const float* z = (const float*)d_in[0];
    const float* emb = (const float*)d_in[1];
    if (n_in >= 2 && in_sizes[1] > in_sizes[0]) {
        const float* t = z; z = emb; emb = t;
    }
    int zsize = in_sizes[0], esize = in_sizes[1];
    if (esize > zsize) { int t = zsize; zsize = esize; esize = t; }

    int N = zsize / DDIM;   // 65536
    int K = esize / DDIM;   // 1024
    float* out = (float*)d_out;
    int write_idx = (out_size >= N * DDIM + N) ? 1 : 0;

    prep_kernel<<<(K + 255) / 256, 256>>>(emb, K);
    vq_kernel<<<N / 128, 256>>>(z, emb, out, N, K, write_idx);
}

// round 11
// speedup vs baseline: 2.4670x; 1.0439x over previous
#include <cuda_runtime.h>
#include <cuda_bf16.h>
#include <cstdint>

// VQ codebook quantization via mma.sync bf16 (3-term split, fp32-exact).
//   s[n,k] = z[n]·e[k] - 0.5*||e[k]||^2 ; idx[n] = argmax_k s ; out = e[idx]
// N=65536, D=64, K=1024. Output: [N*D quantized][N indices-as-float].
//
// R11: 3 independent accumulator sets (one per split term) break the 12-deep
// MMA dependency chain of R10 (tensor pipe was 46% busy, issue 27%); TKC=128
// halves chunk/sync overhead. Final fold: (dh + dl1 + dl2) - cn.

#define DDIM 64
#define TKC  128
#define EPB  144          // bytes per e row in smem (conflict-free ldmatrix)
#define KMAX 1024

__device__ float g_cnorm[KMAX];
__device__ __align__(16) __nv_bfloat16 g_eh[KMAX * DDIM];
__device__ __align__(16) __nv_bfloat16 g_el[KMAX * DDIM];

__global__ void prep_kernel(const float* __restrict__ emb, int K) {
    int k = blockIdx.x * blockDim.x + threadIdx.x;
    if (k < K) {
        float s = 0.f;
#pragma unroll
        for (int d = 0; d < DDIM; d++) {
            float v = emb[(size_t)k * DDIM + d];
            s += v * v;
            __nv_bfloat16 h = __float2bfloat16(v);
            g_eh[(size_t)k * DDIM + d] = h;
            g_el[(size_t)k * DDIM + d] =
                __float2bfloat16(v - __bfloat162float(h));
        }
        g_cnorm[k] = 0.5f * s;
    }
}

__device__ __forceinline__ uint32_t smem_u32(const void* p) {
    uint32_t a;
    asm("{ .reg .u64 t; cvta.to.shared.u64 t, %1; cvt.u32.u64 %0, t; }"
        : "=r"(a) : "l"(p));
    return a;
}
__device__ __forceinline__ uint32_t pack_bf16x2(float x, float y) {
    __nv_bfloat162 h;
    h.x = __float2bfloat16(x);
    h.y = __float2bfloat16(y);
    return *reinterpret_cast<uint32_t*>(&h);
}
__device__ __forceinline__ uint32_t pack_res(float x, float y, uint32_t hp) {
    __nv_bfloat162 h = *reinterpret_cast<__nv_bfloat162*>(&hp);
    __nv_bfloat162 l;
    l.x = __float2bfloat16(x - __bfloat162float(h.x));
    l.y = __float2bfloat16(y - __bfloat162float(h.y));
    return *reinterpret_cast<uint32_t*>(&l);
}
#define MMA16816(d, a0, a1, a2, a3, b0, b1) \
    asm volatile( \
        "mma.sync.aligned.m16n8k16.row.col.f32.bf16.bf16.f32 " \
        "{%0,%1,%2,%3},{%4,%5,%6,%7},{%8,%9},{%0,%1,%2,%3};" \
        : "+f"((d)[0]), "+f"((d)[1]), "+f"((d)[2]), "+f"((d)[3]) \
        : "r"(a0), "r"(a1), "r"(a2), "r"(a3), "r"(b0), "r"(b1))
#define LDMX4(r0, r1, r2, r3, a) \
    asm volatile("ldmatrix.sync.aligned.m8n8.x4.shared.b16 {%0,%1,%2,%3}, [%4];" \
                 : "=r"(r0), "=r"(r1), "=r"(r2), "=r"(r3) : "r"(a))

__global__ __launch_bounds__(256, 2)
void vq_kernel(const float* __restrict__ z, const float* __restrict__ emb,
               float* __restrict__ out, int N, int K, int write_idx) {
    __shared__ float cns[KMAX];                       // 4 KB
    __shared__ __align__(16) char eh_sm[TKC * EPB];   // 18 KB
    __shared__ __align__(16) char el_sm[TKC * EPB];   // 18 KB
    __shared__ int finalIdx[128];

    const int tid = threadIdx.x;
    const int wid = tid >> 5;
    const int lane = tid & 31;
    const int qid = lane >> 2;       // 0..7
    const int qsub = lane & 3;       // 0..3
    const int rowBase = blockIdx.x * 128;

    // ---- build A fragments (zh/zl) for 4 k-steps, once, from gmem ----
    uint32_t ah[4][4], al[4][4];
    {
        const int r0 = rowBase + wid * 16 + qid;
        const int r1 = r0 + 8;
#pragma unroll
        for (int ks = 0; ks < 4; ks++) {
            int k0 = ks * 16 + qsub * 2;
            float2 v00 = *reinterpret_cast<const float2*>(z + (size_t)r0 * DDIM + k0);
            float2 v01 = *reinterpret_cast<const float2*>(z + (size_t)r0 * DDIM + k0 + 8);
            float2 v10 = *reinterpret_cast<const float2*>(z + (size_t)r1 * DDIM + k0);
            float2 v11 = *reinterpret_cast<const float2*>(z + (size_t)r1 * DDIM + k0 + 8);
            ah[ks][0] = pack_bf16x2(v00.x, v00.y);
            ah[ks][1] = pack_bf16x2(v10.x, v10.y);
            ah[ks][2] = pack_bf16x2(v01.x, v01.y);
            ah[ks][3] = pack_bf16x2(v11.x, v11.y);
            al[ks][0] = pack_res(v00.x, v00.y, ah[ks][0]);
            al[ks][1] = pack_res(v10.x, v10.y, ah[ks][1]);
            al[ks][2] = pack_res(v01.x, v01.y, ah[ks][2]);
            al[ks][3] = pack_res(v11.x, v11.y, ah[ks][3]);
        }
    }
    for (int i = tid; i < K; i += 256) cns[i] = g_cnorm[i];

    const uint32_t eh_b = smem_u32(eh_sm);
    const uint32_t el_b = smem_u32(el_sm);

    float bestA = -3.402823466e38f, bestB = -3.402823466e38f;
    int bidxA = 0, bidxB = 0;

    const int nchunks = K / TKC;   // 8
    for (int c = 0; c < nchunks; c++) {
        __syncthreads();
        // stage e chunk: 128 codes x 8 uint4 per term (pitch 144 B)
        {
            const uint4* sh = reinterpret_cast<const uint4*>(
                g_eh + (size_t)c * TKC * DDIM);
            const uint4* sl = reinterpret_cast<const uint4*>(
                g_el + (size_t)c * TKC * DDIM);
#pragma unroll
            for (int t = 0; t < 4; t++) {
                int u = tid + t * 256;
                int code = u >> 3, q = u & 7;
                *reinterpret_cast<uint4*>(eh_sm + code * EPB + q * 16) =
                    sh[code * 8 + q];
                *reinterpret_cast<uint4*>(el_sm + code * EPB + q * 16) =
                    sl[code * 8 + q];
            }
        }
        __syncthreads();

#pragma unroll
        for (int nt = 0; nt < TKC / 8; nt++) {   // 16 n-tiles
            uint32_t lm_off = (nt * 8 + (lane & 7)) * EPB + (lane >> 3) * 16;
            uint32_t bh[8], bl[8];
            LDMX4(bh[0], bh[1], bh[2], bh[3], eh_b + lm_off);        // k 0..31
            LDMX4(bh[4], bh[5], bh[6], bh[7], eh_b + lm_off + 64);   // k 32..63
            LDMX4(bl[0], bl[1], bl[2], bl[3], el_b + lm_off);
            LDMX4(bl[4], bl[5], bl[6], bl[7], el_b + lm_off + 64);

            // 3 independent accumulator chains (4 MMAs each)
            float dh[4] = {0.f, 0.f, 0.f, 0.f};
            float dl1[4] = {0.f, 0.f, 0.f, 0.f};
            float dl2[4] = {0.f, 0.f, 0.f, 0.f};
#pragma unroll
            for (int ks = 0; ks < 4; ks++) {
                MMA16816(dh, ah[ks][0], ah[ks][1], ah[ks][2], ah[ks][3],
                         bh[2 * ks], bh[2 * ks + 1]);
                MMA16816(dl1, ah[ks][0], ah[ks][1], ah[ks][2], ah[ks][3],
                         bl[2 * ks], bl[2 * ks + 1]);
                MMA16816(dl2, al[ks][0], al[ks][1], al[ks][2], al[ks][3],
                         bh[2 * ks], bh[2 * ks + 1]);
            }

            int code0 = c * TKC + nt * 8 + qsub * 2;
            float2 cn = *reinterpret_cast<const float2*>(&cns[code0]);
            float s0 = (dh[0] + dl1[0] + dl2[0]) - cn.x;
            float s1 = (dh[1] + dl1[1] + dl2[1]) - cn.y;
            float s2 = (dh[2] + dl1[2] + dl2[2]) - cn.x;
            float s3 = (dh[3] + dl1[3] + dl2[3]) - cn.y;
            if (s0 > bestA) { bestA = s0; bidxA = code0; }
            if (s1 > bestA) { bestA = s1; bidxA = code0 + 1; }
            if (s2 > bestB) { bestB = s2; bidxB = code0; }
            if (s3 > bestB) { bestB = s3; bidxB = code0 + 1; }
        }
    }

    // ---- quad-lane reduce (same rows in lanes 4q..4q+3), index tie-break ----
#pragma unroll
    for (int off = 1; off < 4; off <<= 1) {
        float vA = __shfl_xor_sync(0xFFFFFFFFu, bestA, off);
        int iA = __shfl_xor_sync(0xFFFFFFFFu, bidxA, off);
        if (vA > bestA || (vA == bestA && iA < bidxA)) { bestA = vA; bidxA = iA; }
        float vB = __shfl_xor_sync(0xFFFFFFFFu, bestB, off);
        int iB = __shfl_xor_sync(0xFFFFFFFFu, bidxB, off);
        if (vB > bestB || (vB == bestB && iB < bidxB)) { bestB = vB; bidxB = iB; }
    }
    if (qsub == 0) {
        finalIdx[wid * 16 + qid] = bidxA;
        finalIdx[wid * 16 + qid + 8] = bidxB;
    }
    __syncthreads();

    if (write_idx && tid < 128)
        out[(size_t)N * DDIM + rowBase + tid] = (float)finalIdx[tid];

    // ---- gather quantized rows (emb rows L2-hot) ----
#pragma unroll
    for (int t = 0; t < 8; t++) {
        int idx = tid + t * 256;
        int row = idx >> 4;
        int c4 = idx & 15;
        float4 v = reinterpret_cast<const float4*>(
            emb + (size_t)finalIdx[row] * DDIM)[c4];
        reinterpret_cast<float4*>(out + (size_t)(rowBase + row) * DDIM)[c4] = v;
    }
}

extern "C" void kernel_launch(void* const* d_in, const int* in_sizes, int n_in,
                              void* d_out, int out_size) {
    const float* z = (const float*)d_in[0];
    const float* emb = (const float*)d_in[1];
    if (n_in >= 2 && in_sizes[1] > in_sizes[0]) {
        const float* t = z; z = emb; emb = t;
    }
    int zsize = in_sizes[0], esize = in_sizes[1];
    if (esize > zsize) { int t = zsize; zsize = esize; esize = t; }

    int N = zsize / DDIM;   // 65536
    int K = esize / DDIM;   // 1024
    float* out = (float*)d_out;
    int write_idx = (out_size >= N * DDIM + N) ? 1 : 0;

    prep_kernel<<<(K + 255) / 256, 256>>>(emb, K);
    vq_kernel<<<N / 128, 256>>>(z, emb, out, N, K, write_idx);
}

// round 12
// speedup vs baseline: 2.6303x; 1.0662x over previous
#include <cuda_runtime.h>
#include <cuda_bf16.h>
#include <cstdint>

// VQ codebook quantization via mma.sync bf16 (3-term split, fp32-exact).
//   s[n,k] = z[n]·e[k] - 0.5*||e[k]||^2 ; idx[n] = argmax_k s ; out = e[idx]
// N=65536, D=64, K=1024. Output: [N*D quantized][N indices-as-float].
//
// R12: 32 rows per warp (2 A-fragment sets) -> 24 MMAs per 4 ldmatrix.x4
// (ratio 6:1, was 3:1), 6 independent MMA chains, CTA covers 256 rows ->
// grid=256 fits one wave (2 CTAs/SM x 148).

#define DDIM 64
#define TKC  128
#define EPB  144          // bytes per e row in smem (conflict-free ldmatrix)
#define KMAX 1024

__device__ float g_cnorm[KMAX];
__device__ __align__(16) __nv_bfloat16 g_eh[KMAX * DDIM];
__device__ __align__(16) __nv_bfloat16 g_el[KMAX * DDIM];

__global__ void prep_kernel(const float* __restrict__ emb, int K) {
    int k = blockIdx.x * blockDim.x + threadIdx.x;
    if (k < K) {
        float s = 0.f;
#pragma unroll
        for (int d = 0; d < DDIM; d++) {
            float v = emb[(size_t)k * DDIM + d];
            s += v * v;
            __nv_bfloat16 h = __float2bfloat16(v);
            g_eh[(size_t)k * DDIM + d] = h;
            g_el[(size_t)k * DDIM + d] =
                __float2bfloat16(v - __bfloat162float(h));
        }
        g_cnorm[k] = 0.5f * s;
    }
}

__device__ __forceinline__ uint32_t smem_u32(const void* p) {
    uint32_t a;
    asm("{ .reg .u64 t; cvta.to.shared.u64 t, %1; cvt.u32.u64 %0, t; }"
        : "=r"(a) : "l"(p));
    return a;
}
__device__ __forceinline__ uint32_t pack_bf16x2(float x, float y) {
    __nv_bfloat162 h;
    h.x = __float2bfloat16(x);
    h.y = __float2bfloat16(y);
    return *reinterpret_cast<uint32_t*>(&h);
}
__device__ __forceinline__ uint32_t pack_res(float x, float y, uint32_t hp) {
    __nv_bfloat162 h = *reinterpret_cast<__nv_bfloat162*>(&hp);
    __nv_bfloat162 l;
    l.x = __float2bfloat16(x - __bfloat162float(h.x));
    l.y = __float2bfloat16(y - __bfloat162float(h.y));
    return *reinterpret_cast<uint32_t*>(&l);
}
#define MMA16816(d, a, b0, b1) \
    asm volatile( \
        "mma.sync.aligned.m16n8k16.row.col.f32.bf16.bf16.f32 " \
        "{%0,%1,%2,%3},{%4,%5,%6,%7},{%8,%9},{%0,%1,%2,%3};" \
        : "+f"((d)[0]), "+f"((d)[1]), "+f"((d)[2]), "+f"((d)[3]) \
        : "r"((a)[0]), "r"((a)[1]), "r"((a)[2]), "r"((a)[3]), "r"(b0), "r"(b1))
#define LDMX4(r0, r1, r2, r3, a) \
    asm volatile("ldmatrix.sync.aligned.m8n8.x4.shared.b16 {%0,%1,%2,%3}, [%4];" \
                 : "=r"(r0), "=r"(r1), "=r"(r2), "=r"(r3) : "r"(a))

// build A fragments for rows (r0, r0+8), 4 k-steps, from gmem z
__device__ __forceinline__ void build_afrag(const float* z, int r0, int qsub,
                                            uint32_t ah[4][4], uint32_t al[4][4]) {
    const int r1 = r0 + 8;
#pragma unroll
    for (int ks = 0; ks < 4; ks++) {
        int k0 = ks * 16 + qsub * 2;
        float2 v00 = *reinterpret_cast<const float2*>(z + (size_t)r0 * DDIM + k0);
        float2 v01 = *reinterpret_cast<const float2*>(z + (size_t)r0 * DDIM + k0 + 8);
        float2 v10 = *reinterpret_cast<const float2*>(z + (size_t)r1 * DDIM + k0);
        float2 v11 = *reinterpret_cast<const float2*>(z + (size_t)r1 * DDIM + k0 + 8);
        ah[ks][0] = pack_bf16x2(v00.x, v00.y);
        ah[ks][1] = pack_bf16x2(v10.x, v10.y);
        ah[ks][2] = pack_bf16x2(v01.x, v01.y);
        ah[ks][3] = pack_bf16x2(v11.x, v11.y);
        al[ks][0] = pack_res(v00.x, v00.y, ah[ks][0]);
        al[ks][1] = pack_res(v10.x, v10.y, ah[ks][1]);
        al[ks][2] = pack_res(v01.x, v01.y, ah[ks][2]);
        al[ks][3] = pack_res(v11.x, v11.y, ah[ks][3]);
    }
}

__global__ __launch_bounds__(256, 2)
void vq_kernel(const float* __restrict__ z, const float* __restrict__ emb,
               float* __restrict__ out, int N, int K, int write_idx) {
    __shared__ float cns[KMAX];                       // 4 KB
    __shared__ __align__(16) char eh_sm[TKC * EPB];   // 18 KB
    __shared__ __align__(16) char el_sm[TKC * EPB];   // 18 KB
    __shared__ int finalIdx[256];

    const int tid = threadIdx.x;
    const int wid = tid >> 5;
    const int lane = tid & 31;
    const int qid = lane >> 2;       // 0..7
    const int qsub = lane & 3;       // 0..3
    const int rowBase = blockIdx.x * 256;

    // ---- A fragments for two 16-row tiles (32 rows per warp) ----
    uint32_t ah0[4][4], al0[4][4], ah1[4][4], al1[4][4];
    const int r0 = rowBase + wid * 32 + qid;
    build_afrag(z, r0, qsub, ah0, al0);
    build_afrag(z, r0 + 16, qsub, ah1, al1);

    for (int i = tid; i < K; i += 256) cns[i] = g_cnorm[i];

    const uint32_t eh_b = smem_u32(eh_sm);
    const uint32_t el_b = smem_u32(el_sm);

    const float NEG = -3.402823466e38f;
    float best[4] = {NEG, NEG, NEG, NEG};   // rows qid, qid+8, qid+16, qid+24
    int bidx[4] = {0, 0, 0, 0};

    const int nchunks = K / TKC;   // 8
    for (int c = 0; c < nchunks; c++) {
        __syncthreads();
        // stage e chunk: 128 codes x 8 uint4 per term (pitch 144 B)
        {
            const uint4* sh = reinterpret_cast<const uint4*>(
                g_eh + (size_t)c * TKC * DDIM);
            const uint4* sl = reinterpret_cast<const uint4*>(
                g_el + (size_t)c * TKC * DDIM);
#pragma unroll
            for (int t = 0; t < 4; t++) {
                int u = tid + t * 256;
                int code = u >> 3, q = u & 7;
                *reinterpret_cast<uint4*>(eh_sm + code * EPB + q * 16) =
                    sh[code * 8 + q];
                *reinterpret_cast<uint4*>(el_sm + code * EPB + q * 16) =
                    sl[code * 8 + q];
            }
        }
        __syncthreads();

#pragma unroll
        for (int nt = 0; nt < TKC / 8; nt++) {   // 16 n-tiles of 8 codes
            uint32_t lm_off = (nt * 8 + (lane & 7)) * EPB + (lane >> 3) * 16;
            uint32_t bh[8], bl[8];
            LDMX4(bh[0], bh[1], bh[2], bh[3], eh_b + lm_off);        // k 0..31
            LDMX4(bh[4], bh[5], bh[6], bh[7], eh_b + lm_off + 64);   // k 32..63
            LDMX4(bl[0], bl[1], bl[2], bl[3], el_b + lm_off);
            LDMX4(bl[4], bl[5], bl[6], bl[7], el_b + lm_off + 64);

            // 6 independent accumulator chains (depth 4 each) = 24 MMAs
            float dh0[4] = {0,0,0,0}, dh1[4] = {0,0,0,0};
            float dp0[4] = {0,0,0,0}, dp1[4] = {0,0,0,0};
            float dq0[4] = {0,0,0,0}, dq1[4] = {0,0,0,0};
#pragma unroll
            for (int ks = 0; ks < 4; ks++) {
                MMA16816(dh0, ah0[ks], bh[2*ks], bh[2*ks+1]);
                MMA16816(dh1, ah1[ks], bh[2*ks], bh[2*ks+1]);
                MMA16816(dp0, ah0[ks], bl[2*ks], bl[2*ks+1]);
                MMA16816(dp1, ah1[ks], bl[2*ks], bl[2*ks+1]);
                MMA16816(dq0, al0[ks], bh[2*ks], bh[2*ks+1]);
                MMA16816(dq1, al1[ks], bh[2*ks], bh[2*ks+1]);
            }

            int code0 = c * TKC + nt * 8 + qsub * 2;
            float2 cn = *reinterpret_cast<const float2*>(&cns[code0]);
            float s;
            s = (dh0[0] + dp0[0] + dq0[0]) - cn.x;
            if (s > best[0]) { best[0] = s; bidx[0] = code0; }
            s = (dh0[1] + dp0[1] + dq0[1]) - cn.y;
            if (s > best[0]) { best[0] = s; bidx[0] = code0 + 1; }
            s = (dh0[2] + dp0[2] + dq0[2]) - cn.x;
            if (s > best[1]) { best[1] = s; bidx[1] = code0; }
            s = (dh0[3] + dp0[3] + dq0[3]) - cn.y;
            if (s > best[1]) { best[1] = s; bidx[1] = code0 + 1; }
            s = (dh1[0] + dp1[0] + dq1[0]) - cn.x;
            if (s > best[2]) { best[2] = s; bidx[2] = code0; }
            s = (dh1[1] + dp1[1] + dq1[1]) - cn.y;
            if (s > best[2]) { best[2] = s; bidx[2] = code0 + 1; }
            s = (dh1[2] + dp1[2] + dq1[2]) - cn.x;
            if (s > best[3]) { best[3] = s; bidx[3] = code0; }
            s = (dh1[3] + dp1[3] + dq1[3]) - cn.y;
            if (s > best[3]) { best[3] = s; bidx[3] = code0 + 1; }
        }
    }

    // ---- quad-lane reduce (rows live in lanes 4q..4q+3), index tie-break ----
#pragma unroll
    for (int off = 1; off < 4; off <<= 1) {
#pragma unroll
        for (int r = 0; r < 4; r++) {
            float v = __shfl_xor_sync(0xFFFFFFFFu, best[r], off);
            int i = __shfl_xor_sync(0xFFFFFFFFu, bidx[r], off);
            if (v > best[r] || (v == best[r] && i < bidx[r])) {
                best[r] = v; bidx[r] = i;
            }
        }
    }
    if (qsub == 0) {
#pragma unroll
        for (int r = 0; r < 4; r++)
            finalIdx[wid * 32 + qid + r * 8] = bidx[r];
    }
    __syncthreads();

    if (write_idx)
        out[(size_t)N * DDIM + rowBase + tid] = (float)finalIdx[tid];

    // ---- gather quantized rows (emb rows L2-hot) ----
#pragma unroll
    for (int t = 0; t < 16; t++) {
        int idx = tid + t * 256;
        int row = idx >> 4;
        int c4 = idx & 15;
        float4 v = reinterpret_cast<const float4*>(
            emb + (size_t)finalIdx[row] * DDIM)[c4];
        reinterpret_cast<float4*>(out + (size_t)(rowBase + row) * DDIM)[c4] = v;
    }
}

extern "C" void kernel_launch(void* const* d_in, const int* in_sizes, int n_in,
                              void* d_out, int out_size) {
    const float* z = (const float*)d_in[0];
    const float* emb = (const float*)d_in[1];
    if (n_in >= 2 && in_sizes[1] > in_sizes[0]) {
        const float* t = z; z = emb; emb = t;
    }
    int zsize = in_sizes[0], esize = in_sizes[1];
    if (esize > zsize) { int t = zsize; zsize = esize; esize = t; }

    int N = zsize / DDIM;   // 65536
    int K = esize / DDIM;   // 1024
    float* out = (float*)d_out;
    int write_idx = (out_size >= N * DDIM + N) ? 1 : 0;

    prep_kernel<<<(K + 255) / 256, 256>>>(emb, K);
    vq_kernel<<<N / 256, 256>>>(z, emb, out, N, K, write_idx);
}

// round 13
// speedup vs baseline: 2.6972x; 1.0254x over previous
#include <cuda_runtime.h>
#include <cuda_bf16.h>
#include <cstdint>

// VQ codebook quantization via mma.sync bf16 (3-term split, fp32-exact).
//   s[n,k] = z[n]·e[k] - 0.5*||e[k]||^2 ; idx[n] = argmax_k s ; out = e[idx]
// N=65536, D=64, K=1024. Output: [N*D quantized][N indices-as-float].
//
// R13: software-pipelined B fragments. Per tile: bh-MMAs (16) run on
// prefetched bh while bl LDSMs land; next tile's bh prefetched mid-burst;
// correction terms share one accumulator set (dc); -cn baked into dh init.

#define DDIM 64
#define TKC  128
#define EPB  144          // bytes per e row in smem (conflict-free ldmatrix)
#define KMAX 1024

__device__ float g_cnorm[KMAX];
__device__ __align__(16) __nv_bfloat16 g_eh[KMAX * DDIM];
__device__ __align__(16) __nv_bfloat16 g_el[KMAX * DDIM];

__global__ void prep_kernel(const float* __restrict__ emb, int K) {
    int k = blockIdx.x * blockDim.x + threadIdx.x;
    if (k < K) {
        float s = 0.f;
#pragma unroll
        for (int d = 0; d < DDIM; d++) {
            float v = emb[(size_t)k * DDIM + d];
            s += v * v;
            __nv_bfloat16 h = __float2bfloat16(v);
            g_eh[(size_t)k * DDIM + d] = h;
            g_el[(size_t)k * DDIM + d] =
                __float2bfloat16(v - __bfloat162float(h));
        }
        g_cnorm[k] = 0.5f * s;
    }
}

__device__ __forceinline__ uint32_t smem_u32(const void* p) {
    uint32_t a;
    asm("{ .reg .u64 t; cvta.to.shared.u64 t, %1; cvt.u32.u64 %0, t; }"
        : "=r"(a) : "l"(p));
    return a;
}
__device__ __forceinline__ uint32_t pack_bf16x2(float x, float y) {
    __nv_bfloat162 h;
    h.x = __float2bfloat16(x);
    h.y = __float2bfloat16(y);
    return *reinterpret_cast<uint32_t*>(&h);
}
__device__ __forceinline__ uint32_t pack_res(float x, float y, uint32_t hp) {
    __nv_bfloat162 h = *reinterpret_cast<__nv_bfloat162*>(&hp);
    __nv_bfloat162 l;
    l.x = __float2bfloat16(x - __bfloat162float(h.x));
    l.y = __float2bfloat16(y - __bfloat162float(h.y));
    return *reinterpret_cast<uint32_t*>(&l);
}
#define MMA16816(d, a, b0, b1) \
    asm volatile( \
        "mma.sync.aligned.m16n8k16.row.col.f32.bf16.bf16.f32 " \
        "{%0,%1,%2,%3},{%4,%5,%6,%7},{%8,%9},{%0,%1,%2,%3};" \
        : "+f"((d)[0]), "+f"((d)[1]), "+f"((d)[2]), "+f"((d)[3]) \
        : "r"((a)[0]), "r"((a)[1]), "r"((a)[2]), "r"((a)[3]), "r"(b0), "r"(b1))
#define LDMX4(r0, r1, r2, r3, a) \
    asm volatile("ldmatrix.sync.aligned.m8n8.x4.shared.b16 {%0,%1,%2,%3}, [%4];" \
                 : "=r"(r0), "=r"(r1), "=r"(r2), "=r"(r3) : "r"(a))

// build A fragments for rows (r0, r0+8), 4 k-steps, from gmem z
__device__ __forceinline__ void build_afrag(const float* z, int r0, int qsub,
                                            uint32_t ah[4][4], uint32_t al[4][4]) {
    const int r1 = r0 + 8;
#pragma unroll
    for (int ks = 0; ks < 4; ks++) {
        int k0 = ks * 16 + qsub * 2;
        float2 v00 = *reinterpret_cast<const float2*>(z + (size_t)r0 * DDIM + k0);
        float2 v01 = *reinterpret_cast<const float2*>(z + (size_t)r0 * DDIM + k0 + 8);
        float2 v10 = *reinterpret_cast<const float2*>(z + (size_t)r1 * DDIM + k0);
        float2 v11 = *reinterpret_cast<const float2*>(z + (size_t)r1 * DDIM + k0 + 8);
        ah[ks][0] = pack_bf16x2(v00.x, v00.y);
        ah[ks][1] = pack_bf16x2(v10.x, v10.y);
        ah[ks][2] = pack_bf16x2(v01.x, v01.y);
        ah[ks][3] = pack_bf16x2(v11.x, v11.y);
        al[ks][0] = pack_res(v00.x, v00.y, ah[ks][0]);
        al[ks][1] = pack_res(v10.x, v10.y, ah[ks][1]);
        al[ks][2] = pack_res(v01.x, v01.y, ah[ks][2]);
        al[ks][3] = pack_res(v11.x, v11.y, ah[ks][3]);
    }
}

__global__ __launch_bounds__(256, 2)
void vq_kernel(const float* __restrict__ z, const float* __restrict__ emb,
               float* __restrict__ out, int N, int K, int write_idx) {
    __shared__ float cns[KMAX];                       // 4 KB
    __shared__ __align__(16) char eh_sm[TKC * EPB];   // 18 KB
    __shared__ __align__(16) char el_sm[TKC * EPB];   // 18 KB
    __shared__ int finalIdx[256];

    const int tid = threadIdx.x;
    const int wid = tid >> 5;
    const int lane = tid & 31;
    const int qid = lane >> 2;       // 0..7
    const int qsub = lane & 3;       // 0..3
    const int rowBase = blockIdx.x * 256;

    // ---- A fragments for two 16-row tiles (32 rows per warp) ----
    uint32_t ah0[4][4], al0[4][4], ah1[4][4], al1[4][4];
    const int r0 = rowBase + wid * 32 + qid;
    build_afrag(z, r0, qsub, ah0, al0);
    build_afrag(z, r0 + 16, qsub, ah1, al1);

    for (int i = tid; i < K; i += 256) cns[i] = g_cnorm[i];

    const uint32_t eh_b = smem_u32(eh_sm);
    const uint32_t el_b = smem_u32(el_sm);
    const uint32_t lm_lane = (lane & 7) * EPB + (lane >> 3) * 16;

    const float NEG = -3.402823466e38f;
    float best[4] = {NEG, NEG, NEG, NEG};   // rows qid, qid+8, qid+16, qid+24
    int bidx[4] = {0, 0, 0, 0};

    const int nchunks = K / TKC;   // 8
    for (int c = 0; c < nchunks; c++) {
        __syncthreads();
        // stage e chunk: 128 codes x 8 uint4 per term (pitch 144 B)
        {
            const uint4* sh = reinterpret_cast<const uint4*>(
                g_eh + (size_t)c * TKC * DDIM);
            const uint4* sl = reinterpret_cast<const uint4*>(
                g_el + (size_t)c * TKC * DDIM);
#pragma unroll
            for (int t = 0; t < 4; t++) {
                int u = tid + t * 256;
                int code = u >> 3, q = u & 7;
                *reinterpret_cast<uint4*>(eh_sm + code * EPB + q * 16) =
                    sh[code * 8 + q];
                *reinterpret_cast<uint4*>(el_sm + code * EPB + q * 16) =
                    sl[code * 8 + q];
            }
        }
        __syncthreads();

        // preload bh for nt=0
        uint32_t bh[8];
        LDMX4(bh[0], bh[1], bh[2], bh[3], eh_b + lm_lane);
        LDMX4(bh[4], bh[5], bh[6], bh[7], eh_b + lm_lane + 64);

#pragma unroll
        for (int nt = 0; nt < TKC / 8; nt++) {   // 16 n-tiles of 8 codes
            // bl for this tile: first consumer is >=16 MMAs away
            uint32_t bl[8];
            uint32_t lm_off = nt * 8 * EPB + lm_lane;
            LDMX4(bl[0], bl[1], bl[2], bl[3], el_b + lm_off);
            LDMX4(bl[4], bl[5], bl[6], bl[7], el_b + lm_off + 64);

            // accumulators: dh pre-biased with -cn; dc holds both corrections
            int code0 = c * TKC + nt * 8 + qsub * 2;
            float2 cn = *reinterpret_cast<const float2*>(&cns[code0]);
            float dh0[4] = {-cn.x, -cn.y, -cn.x, -cn.y};
            float dh1[4] = {-cn.x, -cn.y, -cn.x, -cn.y};
            float dc0[4] = {0, 0, 0, 0};
            float dc1[4] = {0, 0, 0, 0};

            // phase 1: 16 bh-consuming MMAs (zh·eh, zl·eh)
#pragma unroll
            for (int ks = 0; ks < 4; ks++) {
                MMA16816(dh0, ah0[ks], bh[2*ks], bh[2*ks+1]);
                MMA16816(dh1, ah1[ks], bh[2*ks], bh[2*ks+1]);
                MMA16816(dc0, al0[ks], bh[2*ks], bh[2*ks+1]);
                MMA16816(dc1, al1[ks], bh[2*ks], bh[2*ks+1]);
            }

            // prefetch next tile's bh under the bl-MMA burst
            if (nt + 1 < TKC / 8) {
                uint32_t lm_n = (nt + 1) * 8 * EPB + lm_lane;
                LDMX4(bh[0], bh[1], bh[2], bh[3], eh_b + lm_n);
                LDMX4(bh[4], bh[5], bh[6], bh[7], eh_b + lm_n + 64);
            }

            // phase 2: 8 bl-consuming MMAs (zh·el) into dc
#pragma unroll
            for (int ks = 0; ks < 4; ks++) {
                MMA16816(dc0, ah0[ks], bl[2*ks], bl[2*ks+1]);
                MMA16816(dc1, ah1[ks], bl[2*ks], bl[2*ks+1]);
            }

            // fold: s = dh + dc (cn already folded into dh)
            float s;
            s = dh0[0] + dc0[0];
            if (s > best[0]) { best[0] = s; bidx[0] = code0; }
            s = dh0[1] + dc0[1];
            if (s > best[0]) { best[0] = s; bidx[0] = code0 + 1; }
            s = dh0[2] + dc0[2];
            if (s > best[1]) { best[1] = s; bidx[1] = code0; }
            s = dh0[3] + dc0[3];
            if (s > best[1]) { best[1] = s; bidx[1] = code0 + 1; }
            s = dh1[0] + dc1[0];
            if (s > best[2]) { best[2] = s; bidx[2] = code0; }
            s = dh1[1] + dc1[1];
            if (s > best[2]) { best[2] = s; bidx[2] = code0 + 1; }
            s = dh1[2] + dc1[2];
            if (s > best[3]) { best[3] = s; bidx[3] = code0; }
            s = dh1[3] + dc1[3];
            if (s > best[3]) { best[3] = s; bidx[3] = code0 + 1; }
        }
    }

    // ---- quad-lane reduce (rows live in lanes 4q..4q+3), index tie-break ----
#pragma unroll
    for (int off = 1; off < 4; off <<= 1) {
#pragma unroll
        for (int r = 0; r < 4; r++) {
            float v = __shfl_xor_sync(0xFFFFFFFFu, best[r], off);
            int i = __shfl_xor_sync(0xFFFFFFFFu, bidx[r], off);
            if (v > best[r] || (v == best[r] && i < bidx[r])) {
                best[r] = v; bidx[r] = i;
            }
        }
    }
    if (qsub == 0) {
#pragma unroll
        for (int r = 0; r < 4; r++)
            finalIdx[wid * 32 + qid + r * 8] = bidx[r];
    }
    __syncthreads();

    if (write_idx)
        out[(size_t)N * DDIM + rowBase + tid] = (float)finalIdx[tid];

    // ---- gather quantized rows (emb rows L2-hot) ----
#pragma unroll
    for (int t = 0; t < 16; t++) {
        int idx = tid + t * 256;
        int row = idx >> 4;
        int c4 = idx & 15;
        float4 v = reinterpret_cast<const float4*>(
            emb + (size_t)finalIdx[row] * DDIM)[c4];
        reinterpret_cast<float4*>(out + (size_t)(rowBase + row) * DDIM)[c4] = v;
    }
}

extern "C" void kernel_launch(void* const* d_in, const int* in_sizes, int n_in,
                              void* d_out, int out_size) {
    const float* z = (const float*)d_in[0];
    const float* emb = (const float*)d_in[1];
    if (n_in >= 2 && in_sizes[1] > in_sizes[0]) {
        const float* t = z; z = emb; emb = t;
    }
    int zsize = in_sizes[0], esize = in_sizes[1];
    if (esize > zsize) { int t = zsize; zsize = esize; esize = t; }

    int N = zsize / DDIM;   // 65536
    int K = esize / DDIM;   // 1024
    float* out = (float*)d_out;
    int write_idx = (out_size >= N * DDIM + N) ? 1 : 0;

    prep_kernel<<<(K + 255) / 256, 256>>>(emb, K);
    vq_kernel<<<N / 256, 256>>>(z, emb, out, N, K, write_idx);
}